// round 1
// baseline (speedup 1.0000x reference)
#include <cuda_runtime.h>
#include <cstdint>
#include <math.h>

#define BB 8
#define CC_ 128
#define HH 64
#define WW 64
#define NPH 32
#define NP 1024

typedef unsigned long long u64;

// ---------------- scratch (device globals; no allocs allowed) ----------------
__device__ float d_xdT[BB * 2 * CC_ * NP];              // [b][p][c][n]  8 MB
__device__ float d_corr[(size_t)BB * 2 * NP * NP];      // [b][p][n][m] 64 MB
__device__ float d_inv[BB * 3 * NP];                    // [b][ch][n] 1/rowsum

// ---------------- helpers ----------------
__device__ __forceinline__ u64 pack2(float lo, float hi) {
    u64 r;
    asm("mov.b64 %0, {%1, %2};" : "=l"(r) : "f"(lo), "f"(hi));
    return r;
}
__device__ __forceinline__ void unpack2(u64 v, float& lo, float& hi) {
    asm("mov.b64 {%0, %1}, %2;" : "=f"(lo), "=f"(hi) : "l"(v));
}
__device__ __forceinline__ void ffma2(u64& d, u64 a, u64 b) {
    asm("fma.rn.f32x2 %0, %1, %2, %0;" : "+l"(d) : "l"(a), "l"(b));
}
__device__ __forceinline__ u64 umax64(u64 a, u64 b) { return a > b ? a : b; }

// ================= K1: L2-normalize over C, extract diagonal pixels =========
// block = (b, h), 256 threads. xdT[b][p][c][n] with p = h&1, n = (h/2)*32 + w/2
__global__ void __launch_bounds__(256) k1_norm(const float* __restrict__ x) {
    __shared__ float xs[CC_ * WW];   // 32 KB: [c][w]
    __shared__ float ssp[4][WW];
    __shared__ float invn[WW];
    int b = blockIdx.y, h = blockIdx.x;
    int tid = threadIdx.x;
    const float* xrow = x + (size_t)b * CC_ * HH * WW + (size_t)h * WW;
    for (int idx = tid; idx < CC_ * WW; idx += 256) {
        int c = idx >> 6, w = idx & 63;
        xs[idx] = xrow[(size_t)c * HH * WW + w];
    }
    __syncthreads();
    {
        int w = tid & 63, c4 = tid >> 6;
        float ss = 0.f;
        #pragma unroll 8
        for (int c = c4 * 32; c < c4 * 32 + 32; c++) {
            float v = xs[c * WW + w];
            ss += v * v;
        }
        ssp[c4][w] = ss;
    }
    __syncthreads();
    if (tid < WW) {
        float s = ssp[0][tid] + ssp[1][tid] + ssp[2][tid] + ssp[3][tid];
        invn[tid] = 1.0f / fmaxf(sqrtf(s), 1e-12f);
    }
    __syncthreads();
    int p = h & 1;
    int nbase = (h >> 1) * NPH;
    float* outb = d_xdT + ((size_t)(b * 2 + p) * CC_) * NP + nbase;
    for (int idx = tid; idx < CC_ * NPH; idx += 256) {
        int c = idx >> 5, j = idx & 31;
        int w = 2 * j + p;
        outb[(size_t)c * NP + j] = xs[c * WW + w] * invn[w];
    }
}

// ================= K2: corr[z][n][m] = sum_c X[z][c][n]*X[z][c][m] ==========
// z = b*2+p (16 batches). 128x128 tile per block, BK=32, 256 threads, 8x8/thr,
// packed fp32x2 FMA (exact fp32 math, 2x FFMA issue throughput).
__global__ void __launch_bounds__(256, 2) k2_gemm() {
    __shared__ float As[32][128];
    __shared__ float Bs[32][128];
    const float* Xz = d_xdT + (size_t)blockIdx.z * (CC_ * NP);
    float* Cz = d_corr + (size_t)blockIdx.z * NP * NP;
    int n0 = blockIdx.y * 128, m0 = blockIdx.x * 128;
    int tid = threadIdx.x;
    int tx = tid & 15, ty = tid >> 4;

    u64 acc[8][4];
    #pragma unroll
    for (int i = 0; i < 8; i++)
        #pragma unroll
        for (int j = 0; j < 4; j++) acc[i][j] = 0ULL;   // {0.f,0.f}

    int lr = tid >> 5;            // 0..7
    int lc = (tid & 31) * 4;      // 0..124

    for (int kk = 0; kk < CC_; kk += 32) {
        #pragma unroll
        for (int s = 0; s < 4; s++) {
            int c = lr + s * 8;
            const float* src = Xz + (size_t)(kk + c) * NP;
            *(float4*)&As[c][lc] = *(const float4*)(src + n0 + lc);
            *(float4*)&Bs[c][lc] = *(const float4*)(src + m0 + lc);
        }
        __syncthreads();
        #pragma unroll
        for (int cc = 0; cc < 32; cc++) {
            float4 a0 = *(float4*)&As[cc][ty * 8];
            float4 a1 = *(float4*)&As[cc][ty * 8 + 4];
            float4 b0 = *(float4*)&Bs[cc][tx * 8];
            float4 b1 = *(float4*)&Bs[cc][tx * 8 + 4];
            u64 bb[4] = { pack2(b0.x, b0.y), pack2(b0.z, b0.w),
                          pack2(b1.x, b1.y), pack2(b1.z, b1.w) };
            float av[8] = { a0.x, a0.y, a0.z, a0.w, a1.x, a1.y, a1.z, a1.w };
            #pragma unroll
            for (int i = 0; i < 8; i++) {
                u64 aa = pack2(av[i], av[i]);
                #pragma unroll
                for (int j = 0; j < 4; j++) ffma2(acc[i][j], aa, bb[j]);
            }
        }
        __syncthreads();
    }
    #pragma unroll
    for (int i = 0; i < 8; i++) {
        float v[8];
        #pragma unroll
        for (int j = 0; j < 4; j++) unpack2(acc[i][j], v[2 * j], v[2 * j + 1]);
        float* dst = Cz + (size_t)(n0 + ty * 8 + i) * NP + m0 + tx * 8;
        *(float4*)(dst) = make_float4(v[0], v[1], v[2], v[3]);
        *(float4*)(dst + 4) = make_float4(v[4], v[5], v[6], v[7]);
    }
}

// ================= K3: per-row sums of exp(a) for the 3 channels ============
// A is symmetric => these also serve as column stats. No max-subtraction
// needed (|a| <= alpha = 5). 8 warps/block, 1 row per warp.
__global__ void __launch_bounds__(256) k3_rowsum(const float* __restrict__ alphap) {
    __shared__ float er[NPH];
    int tid = threadIdx.x;
    if (tid < NPH) er[tid] = expf(-(float)(tid * tid) / 5.12f);  // 2*(0.05*32)^2
    __syncthreads();
    float alpha = *alphap;
    int b = blockIdx.x >> 7;
    int rowblk = blockIdx.x & 127;
    int warp = tid >> 5, lane = tid & 31;
    int n = rowblk * 8 + warp;
    int rn = n >> 5, cn = n & 31;
    const float* r0 = d_corr + ((size_t)(b * 2 + 0) * NP + n) * NP;
    const float* r1 = d_corr + ((size_t)(b * 2 + 1) * NP + n) * NP;
    float ec = er[abs(cn - lane)];   // cm == lane for every iteration
    float s0 = 0.f, s1 = 0.f, s2 = 0.f;
    #pragma unroll 4
    for (int i = 0; i < 32; i++) {   // rm == i
        int m = lane + i * 32;
        float v0 = r0[m], v1 = r1[m];
        float f = alpha * (1.0f - er[abs(rn - i)] * ec);
        s0 += __expf(v0 * f);
        s1 += __expf(v1 * f);
        s2 += __expf((v0 + v1) * 0.5f * f);
    }
    #pragma unroll
    for (int off = 16; off; off >>= 1) {
        s0 += __shfl_xor_sync(0xffffffffu, s0, off);
        s1 += __shfl_xor_sync(0xffffffffu, s1, off);
        s2 += __shfl_xor_sync(0xffffffffu, s2, off);
    }
    if (lane == 0) {
        d_inv[(b * 3 + 0) * NP + n] = 1.0f / s0;
        d_inv[(b * 3 + 1) * NP + n] = 1.0f / s1;
        d_inv[(b * 3 + 2) * NP + n] = 1.0f / s2;
    }
}

// ================= K4: S = e^2 * inv[n] * inv[m], top-3 per row, scatter ====
// block = (b, n), 256 threads, 4 m-values/thread. Top-3 via 3 rounds of block
// argmax (S > 0 strictly, so 0.0f works as the "removed" sentinel and
// positive-float bit patterns are order-preserving as unsigned).
__global__ void __launch_bounds__(256) k4_final(const float* __restrict__ alphap,
                                                float* __restrict__ out) {
    __shared__ float er[NPH];
    __shared__ u64 red[8];
    __shared__ u64 winner_s;
    __shared__ float topv[3][3];
    int tid = threadIdx.x;
    if (tid < NPH) er[tid] = expf(-(float)(tid * tid) / 5.12f);
    __syncthreads();
    float alpha = *alphap;
    int b = blockIdx.x >> 10;
    int n = blockIdx.x & 1023;
    int rn = n >> 5, cn = n & 31;
    const float* r0 = d_corr + ((size_t)(b * 2) * NP + n) * NP;
    const float* r1 = r0 + (size_t)NP * NP;
    float in0 = d_inv[(b * 3 + 0) * NP + n];
    float in1 = d_inv[(b * 3 + 1) * NP + n];
    float in2 = d_inv[(b * 3 + 2) * NP + n];

    float s[3][4];
    #pragma unroll
    for (int i = 0; i < 4; i++) {
        int m = tid + i * 256;
        int rm = m >> 5, cm = m & 31;
        float f = alpha * (1.0f - er[abs(rn - rm)] * er[abs(cn - cm)]);
        float v0 = r0[m], v1 = r1[m];
        float e0 = __expf(v0 * f);
        float e1 = __expf(v1 * f);
        float e2 = __expf((v0 + v1) * 0.5f * f);
        s[0][i] = e0 * e0 * in0 * d_inv[(b * 3 + 0) * NP + m];
        s[1][i] = e1 * e1 * in1 * d_inv[(b * 3 + 1) * NP + m];
        s[2][i] = e2 * e2 * in2 * d_inv[(b * 3 + 2) * NP + m];
    }

    int warp = tid >> 5, lane = tid & 31;
    for (int ch = 0; ch < 3; ch++) {
        for (int r = 0; r < 3; r++) {
            u64 best = 0;
            #pragma unroll
            for (int i = 0; i < 4; i++) {
                u64 key = ((u64)__float_as_uint(s[ch][i]) << 32) |
                          (unsigned)(tid + i * 256);
                best = umax64(best, key);
            }
            #pragma unroll
            for (int off = 16; off; off >>= 1)
                best = umax64(best, __shfl_xor_sync(0xffffffffu, best, off));
            if (lane == 0) red[warp] = best;
            __syncthreads();
            if (tid < 8) {
                u64 bb = red[tid];
                #pragma unroll
                for (int off = 4; off; off >>= 1)
                    bb = umax64(bb, __shfl_xor_sync(0x000000ffu, bb, off));
                if (tid == 0) {
                    winner_s = bb;
                    topv[ch][r] = __uint_as_float((unsigned)(bb >> 32));
                }
            }
            __syncthreads();
            int wm = (int)(winner_s & 0xffffffffULL);
            if ((wm & 255) == tid) s[ch][wm >> 8] = 0.0f;  // remove winner
        }
    }
    __syncthreads();
    if (tid < 12) {
        int pix = tid & 3, k = tid >> 2;
        int chn = (pix == 0) ? 0 : ((pix == 3) ? 1 : 2);
        int hh = 2 * rn + (pix >> 1);
        int ww = 2 * cn + (pix & 1);
        out[(((size_t)b * 3 + k) * HH + hh) * WW + ww] = topv[chn][k];
    }
}

// ================= launch ====================================================
extern "C" void kernel_launch(void* const* d_in, const int* in_sizes, int n_in,
                              void* d_out, int out_size) {
    const float* x = (const float*)d_in[0];
    const float* alpha = (const float*)d_in[1];
    float* out = (float*)d_out;

    k1_norm<<<dim3(HH, BB), 256>>>(x);
    k2_gemm<<<dim3(8, 8, 16), 256>>>();
    k3_rowsum<<<1024, 256>>>(alpha);
    k4_final<<<8192, 256>>>(alpha, out);
}

// round 2
// speedup vs baseline: 1.5421x; 1.5421x over previous
#include <cuda_runtime.h>
#include <cstdint>
#include <math.h>

#define BB 8
#define CC_ 128
#define HH 64
#define WW 64
#define NPH 32
#define NP 1024

typedef unsigned long long u64;

// ---------------- scratch (device globals; no allocs allowed) ----------------
__device__ float d_xdT[BB * 2 * CC_ * NP];              // [b][p][c][n]  8 MB
__device__ float d_corr[(size_t)BB * 2 * NP * NP];      // [b][p][n][m] 64 MB
__device__ float d_inv[BB * 3 * NP];                    // [b][ch][n] 1/rowsum

// ---------------- helpers ----------------
__device__ __forceinline__ u64 pack2(float lo, float hi) {
    u64 r;
    asm("mov.b64 %0, {%1, %2};" : "=l"(r) : "f"(lo), "f"(hi));
    return r;
}
__device__ __forceinline__ void unpack2(u64 v, float& lo, float& hi) {
    asm("mov.b64 {%0, %1}, %2;" : "=f"(lo), "=f"(hi) : "l"(v));
}
__device__ __forceinline__ void ffma2(u64& d, u64 a, u64 b) {
    asm("fma.rn.f32x2 %0, %1, %2, %0;" : "+l"(d) : "l"(a), "l"(b));
}

// ================= K1: L2-normalize over C, extract diagonal pixels =========
__global__ void __launch_bounds__(256) k1_norm(const float* __restrict__ x) {
    __shared__ float xs[CC_ * WW];
    __shared__ float ssp[4][WW];
    __shared__ float invn[WW];
    int b = blockIdx.y, h = blockIdx.x;
    int tid = threadIdx.x;
    const float* xrow = x + (size_t)b * CC_ * HH * WW + (size_t)h * WW;
    for (int idx = tid; idx < CC_ * WW; idx += 256) {
        int c = idx >> 6, w = idx & 63;
        xs[idx] = xrow[(size_t)c * HH * WW + w];
    }
    __syncthreads();
    {
        int w = tid & 63, c4 = tid >> 6;
        float ss = 0.f;
        #pragma unroll 8
        for (int c = c4 * 32; c < c4 * 32 + 32; c++) {
            float v = xs[c * WW + w];
            ss += v * v;
        }
        ssp[c4][w] = ss;
    }
    __syncthreads();
    if (tid < WW) {
        float s = ssp[0][tid] + ssp[1][tid] + ssp[2][tid] + ssp[3][tid];
        invn[tid] = 1.0f / fmaxf(sqrtf(s), 1e-12f);
    }
    __syncthreads();
    int p = h & 1;
    int nbase = (h >> 1) * NPH;
    float* outb = d_xdT + ((size_t)(b * 2 + p) * CC_) * NP + nbase;
    for (int idx = tid; idx < CC_ * NPH; idx += 256) {
        int c = idx >> 5, j = idx & 31;
        int w = 2 * j + p;
        outb[(size_t)c * NP + j] = xs[c * WW + w] * invn[w];
    }
}

// ================= K2: symmetric Gram GEMM, upper-triangle tiles only =======
// corr[z][n][m] = sum_c X[z][c][n]*X[z][c][m] is symmetric: compute 36 of 64
// 128x128 tiles, store off-diagonal tiles twice (normal + transposed).
__global__ void __launch_bounds__(256, 2) k2_gemm() {
    __shared__ float As[32][128];
    __shared__ float Bs[32][128];
    // decode upper-triangle tile index
    int u = blockIdx.x, ti = 0;
    for (;;) { int row = 8 - ti; if (u < row) break; u -= row; ti++; }
    int tj = ti + u;
    int n0 = ti * 128, m0 = tj * 128;

    const float* Xz = d_xdT + (size_t)blockIdx.y * (CC_ * NP);
    float* Cz = d_corr + (size_t)blockIdx.y * NP * NP;
    int tid = threadIdx.x;
    int tx = tid & 15, ty = tid >> 4;

    u64 acc[8][4];
    #pragma unroll
    for (int i = 0; i < 8; i++)
        #pragma unroll
        for (int j = 0; j < 4; j++) acc[i][j] = 0ULL;

    int lr = tid >> 5;
    int lc = (tid & 31) * 4;

    for (int kk = 0; kk < CC_; kk += 32) {
        #pragma unroll
        for (int s = 0; s < 4; s++) {
            int c = lr + s * 8;
            const float* src = Xz + (size_t)(kk + c) * NP;
            *(float4*)&As[c][lc] = *(const float4*)(src + n0 + lc);
            *(float4*)&Bs[c][lc] = *(const float4*)(src + m0 + lc);
        }
        __syncthreads();
        #pragma unroll
        for (int cc = 0; cc < 32; cc++) {
            float4 a0 = *(float4*)&As[cc][ty * 8];
            float4 a1 = *(float4*)&As[cc][ty * 8 + 4];
            float4 b0 = *(float4*)&Bs[cc][tx * 8];
            float4 b1 = *(float4*)&Bs[cc][tx * 8 + 4];
            u64 bb[4] = { pack2(b0.x, b0.y), pack2(b0.z, b0.w),
                          pack2(b1.x, b1.y), pack2(b1.z, b1.w) };
            float av[8] = { a0.x, a0.y, a0.z, a0.w, a1.x, a1.y, a1.z, a1.w };
            #pragma unroll
            for (int i = 0; i < 8; i++) {
                u64 aa = pack2(av[i], av[i]);
                #pragma unroll
                for (int j = 0; j < 4; j++) ffma2(acc[i][j], aa, bb[j]);
            }
        }
        __syncthreads();
    }

    float v[8][8];
    #pragma unroll
    for (int i = 0; i < 8; i++)
        #pragma unroll
        for (int j = 0; j < 4; j++)
            unpack2(acc[i][j], v[i][2 * j], v[i][2 * j + 1]);

    // normal store: rows n0+ty*8+i, cols m0+tx*8..+7
    #pragma unroll
    for (int i = 0; i < 8; i++) {
        float* dst = Cz + (size_t)(n0 + ty * 8 + i) * NP + m0 + tx * 8;
        *(float4*)(dst)     = make_float4(v[i][0], v[i][1], v[i][2], v[i][3]);
        *(float4*)(dst + 4) = make_float4(v[i][4], v[i][5], v[i][6], v[i][7]);
    }
    // transposed store for off-diagonal tiles: rows m0+tx*8+jj, cols n0+ty*8..+7
    if (ti != tj) {
        #pragma unroll
        for (int jj = 0; jj < 8; jj++) {
            float* dst = Cz + (size_t)(m0 + tx * 8 + jj) * NP + n0 + ty * 8;
            *(float4*)(dst)     = make_float4(v[0][jj], v[1][jj], v[2][jj], v[3][jj]);
            *(float4*)(dst + 4) = make_float4(v[4][jj], v[5][jj], v[6][jj], v[7][jj]);
        }
    }
}

// ================= K3: per-row sums of exp(a) for the 3 channels ============
__global__ void __launch_bounds__(256) k3_rowsum(const float* __restrict__ alphap) {
    __shared__ float er[NPH];
    int tid = threadIdx.x;
    if (tid < NPH) er[tid] = expf(-(float)(tid * tid) / 5.12f);
    __syncthreads();
    float alpha = *alphap;
    int b = blockIdx.x >> 7;
    int rowblk = blockIdx.x & 127;
    int warp = tid >> 5, lane = tid & 31;
    int n = rowblk * 8 + warp;
    int rn = n >> 5, cn = n & 31;
    const float* r0 = d_corr + ((size_t)(b * 2 + 0) * NP + n) * NP;
    const float* r1 = d_corr + ((size_t)(b * 2 + 1) * NP + n) * NP;
    float ec = er[abs(cn - lane)];
    float s0 = 0.f, s1 = 0.f, s2 = 0.f;
    #pragma unroll 4
    for (int i = 0; i < 32; i++) {
        int m = lane + i * 32;
        float v0 = r0[m], v1 = r1[m];
        float f = alpha * (1.0f - er[abs(rn - i)] * ec);
        s0 += __expf(v0 * f);
        s1 += __expf(v1 * f);
        s2 += __expf((v0 + v1) * 0.5f * f);
    }
    #pragma unroll
    for (int off = 16; off; off >>= 1) {
        s0 += __shfl_xor_sync(0xffffffffu, s0, off);
        s1 += __shfl_xor_sync(0xffffffffu, s1, off);
        s2 += __shfl_xor_sync(0xffffffffu, s2, off);
    }
    if (lane == 0) {
        d_inv[(b * 3 + 0) * NP + n] = 1.0f / s0;
        d_inv[(b * 3 + 1) * NP + n] = 1.0f / s1;
        d_inv[(b * 3 + 2) * NP + n] = 1.0f / s2;
    }
}

// ---- top-3 insertion into sorted registers (t0 >= t1 >= t2) ----
__device__ __forceinline__ void ins3(float v, float& t0, float& t1, float& t2) {
    if (v > t2) {
        if (v > t1) {
            t2 = t1;
            if (v > t0) { t1 = t0; t0 = v; }
            else t1 = v;
        } else t2 = v;
    }
}
// ---- merge two sorted 3-lists -> top3 of the union ----
__device__ __forceinline__ void merge3(float& a0, float& a1, float& a2,
                                       float b0, float b1, float b2) {
    float mx0 = fmaxf(a0, b0), mn0 = fminf(a0, b0);
    float mx1 = fmaxf(a1, b1);
    float mx2 = fmaxf(a2, b2);
    a0 = mx0;
    a1 = fmaxf(mn0, mx1);
    a2 = fmaxf(fminf(mn0, mx1), mx2);
}

// ================= K4: S = e^2*inv[n]*inv[m], top-3 per row, scatter ========
// One warp per (b,n) row, 32 m per lane, per-lane top-3 + butterfly merge.
// e2^2 = e0*e1 -> only 2 exps per element. inv[n] applied post-selection.
__global__ void __launch_bounds__(256) k4_final(const float* __restrict__ alphap,
                                                float* __restrict__ out) {
    __shared__ float er_s[NPH];
    __shared__ float inv_s[3][NP];
    int tid = threadIdx.x;
    int b = blockIdx.x >> 7;
    int rowblk = blockIdx.x & 127;
    if (tid < NPH) er_s[tid] = expf(-(float)(tid * tid) / 5.12f);
    for (int idx = tid; idx < 3 * NP; idx += 256)
        ((float*)inv_s)[idx] = d_inv[b * 3 * NP + idx];
    __syncthreads();

    float alpha = *alphap;
    int warp = tid >> 5, lane = tid & 31;
    int n = rowblk * 8 + warp;
    int rn = n >> 5, cn = n & 31;
    const float* r0 = d_corr + ((size_t)(b * 2) * NP + n) * NP;
    const float* r1 = r0 + (size_t)NP * NP;
    float ec_al = alpha * er_s[abs(cn - lane)];

    float t00 = 0.f, t01 = 0.f, t02 = 0.f;
    float t10 = 0.f, t11 = 0.f, t12 = 0.f;
    float t20 = 0.f, t21 = 0.f, t22 = 0.f;

    #pragma unroll 4
    for (int i = 0; i < 32; i++) {
        int m = i * 32 + lane;
        float v0 = __ldg(r0 + m);
        float v1 = __ldg(r1 + m);
        float f = alpha - er_s[abs(rn - i)] * ec_al;
        float e0 = __expf(v0 * f);
        float e1 = __expf(v1 * f);
        float s0 = e0 * e0 * inv_s[0][m];
        float s1 = e1 * e1 * inv_s[1][m];
        float s2 = e0 * e1 * inv_s[2][m];
        ins3(s0, t00, t01, t02);
        ins3(s1, t10, t11, t12);
        ins3(s2, t20, t21, t22);
    }
    #pragma unroll
    for (int off = 16; off; off >>= 1) {
        float b0, b1, b2;
        b0 = __shfl_xor_sync(0xffffffffu, t00, off);
        b1 = __shfl_xor_sync(0xffffffffu, t01, off);
        b2 = __shfl_xor_sync(0xffffffffu, t02, off);
        merge3(t00, t01, t02, b0, b1, b2);
        b0 = __shfl_xor_sync(0xffffffffu, t10, off);
        b1 = __shfl_xor_sync(0xffffffffu, t11, off);
        b2 = __shfl_xor_sync(0xffffffffu, t12, off);
        merge3(t10, t11, t12, b0, b1, b2);
        b0 = __shfl_xor_sync(0xffffffffu, t20, off);
        b1 = __shfl_xor_sync(0xffffffffu, t21, off);
        b2 = __shfl_xor_sync(0xffffffffu, t22, off);
        merge3(t20, t21, t22, b0, b1, b2);
    }
    // every lane now holds the row's top-3 for all 3 channels
    if (lane < 12) {
        int k = lane >> 2, pix = lane & 3;
        int chn = (pix == 0) ? 0 : ((pix == 3) ? 1 : 2);
        float a0 = (chn == 0) ? t00 : (chn == 1) ? t10 : t20;
        float a1 = (chn == 0) ? t01 : (chn == 1) ? t11 : t21;
        float a2 = (chn == 0) ? t02 : (chn == 1) ? t12 : t22;
        float val = (k == 0) ? a0 : (k == 1) ? a1 : a2;
        val *= inv_s[chn][n];     // deferred row constant
        int hh = 2 * rn + (pix >> 1);
        int ww = 2 * cn + (pix & 1);
        out[(((size_t)b * 3 + k) * HH + hh) * WW + ww] = val;
    }
}

// ================= launch ====================================================
extern "C" void kernel_launch(void* const* d_in, const int* in_sizes, int n_in,
                              void* d_out, int out_size) {
    const float* x = (const float*)d_in[0];
    const float* alpha = (const float*)d_in[1];
    float* out = (float*)d_out;

    k1_norm<<<dim3(HH, BB), 256>>>(x);
    k2_gemm<<<dim3(36, 16), 256>>>();
    k3_rowsum<<<1024, 256>>>(alpha);
    k4_final<<<1024, 256>>>(alpha, out);
}

// round 4
// speedup vs baseline: 1.7342x; 1.1246x over previous
#include <cuda_runtime.h>
#include <cuda_bf16.h>
#include <cstdint>
#include <math.h>

#define BB 8
#define CC_ 128
#define HH 64
#define WW 64
#define NPH 32
#define NP 1024

typedef unsigned long long u64;

// ---------------- scratch (device globals; no allocs allowed) ----------------
__device__ __nv_bfloat16 d_xhi[16 * NP * CC_];          // [z][n][c] 4 MB
__device__ __nv_bfloat16 d_xlo[16 * NP * CC_];          // [z][n][c] 4 MB
__device__ float d_corr[(size_t)16 * NP * NP];          // [z][n][m] 64 MB
__device__ float d_inv[BB * 3 * NP];                    // [b][ch][n]

// ---------------- baseline-PTX tensor core helpers (sm_80+) ----------------
__device__ __forceinline__ uint32_t smem_to_u32(const void* p) {
    uint32_t a;
    asm("{ .reg .u64 t; cvta.to.shared.u64 t, %1; cvt.u32.u64 %0, t; }"
        : "=r"(a) : "l"(p));
    return a;
}
#define LDSM_X4(r, addr) \
    asm volatile("ldmatrix.sync.aligned.m8n8.x4.shared.b16 {%0,%1,%2,%3}, [%4];" \
        : "=r"((r)[0]), "=r"((r)[1]), "=r"((r)[2]), "=r"((r)[3]) : "r"(addr))
#define MMA16816(c, a, b) \
    asm volatile("mma.sync.aligned.m16n8k16.row.col.f32.bf16.bf16.f32 " \
        "{%0,%1,%2,%3}, {%4,%5,%6,%7}, {%8,%9}, {%0,%1,%2,%3};" \
        : "+f"((c)[0]), "+f"((c)[1]), "+f"((c)[2]), "+f"((c)[3]) \
        : "r"((a)[0]), "r"((a)[1]), "r"((a)[2]), "r"((a)[3]), \
          "r"((b)[0]), "r"((b)[1]))

// swizzled smem byte offset for bf16 operand tile [128 rows][16 x 16B chunks]
__device__ __forceinline__ uint32_t sw_off(int row, int c16) {
    return (uint32_t)((((row << 1) + (c16 >> 3)) << 7) |
                      ((((c16 & 7) ^ (row & 7))) << 4));
}

// ================= K1: L2-normalize over C, extract diag pixels, bf16 split =
__global__ void __launch_bounds__(256) k1_norm(const float* __restrict__ x) {
    __shared__ float xs[CC_ * 65];
    __shared__ float ssp[4][WW];
    __shared__ float invn[WW];
    int b = blockIdx.y, h = blockIdx.x;
    int tid = threadIdx.x;
    const float* xrow = x + (size_t)b * CC_ * HH * WW + (size_t)h * WW;
    for (int idx = tid; idx < CC_ * WW; idx += 256) {
        int c = idx >> 6, w = idx & 63;
        xs[c * 65 + w] = xrow[(size_t)c * HH * WW + w];
    }
    __syncthreads();
    {
        int w = tid & 63, c4 = tid >> 6;
        float ss = 0.f;
        #pragma unroll 8
        for (int c = c4 * 32; c < c4 * 32 + 32; c++) {
            float v = xs[c * 65 + w];
            ss += v * v;
        }
        ssp[c4][w] = ss;
    }
    __syncthreads();
    if (tid < WW) {
        float s = ssp[0][tid] + ssp[1][tid] + ssp[2][tid] + ssp[3][tid];
        invn[tid] = 1.0f / fmaxf(sqrtf(s), 1e-12f);
    }
    __syncthreads();
    int p = h & 1;
    int z = b * 2 + p;
    int nb = (h >> 1) * NPH;
    for (int idx = tid; idx < NPH * CC_; idx += 256) {
        int j = idx >> 7, c = idx & 127;
        int w = 2 * j + p;
        float v = xs[c * 65 + w] * invn[w];
        __nv_bfloat16 hi = __float2bfloat16(v);
        float lo = v - __bfloat162float(hi);
        size_t o = ((size_t)z * NP + nb + j) * CC_ + c;
        d_xhi[o] = hi;
        d_xlo[o] = __float2bfloat16(lo);
    }
}

// ================= K2: mma.sync bf16 split Gram GEMM (triangle tiles) =======
// corr[z][n][m] = X[n]·X[m]; 3 terms hi.hi + hi.lo + lo.hi. 128x128 tiles,
// ti<=tj only; epilogue stages fp32 tile in smem, stores normal + transposed.
#define OFF_AHI 0
#define OFF_ALO 32768
#define OFF_BHI 65536
#define OFF_BLO 98304
#define K2_SMEM 131072
#define STG_LD  132

__global__ void __launch_bounds__(256) k2_gemm() {
    extern __shared__ char sm[];
    uint32_t smem_base = smem_to_u32(sm);
    int tid = threadIdx.x;
    int wid = tid >> 5, lane = tid & 31;
    int wm = wid & 3, wn = wid >> 2;

    // triangle tile decode
    int u = blockIdx.x, ti = 0;
    for (;;) { int row = 8 - ti; if (u < row) break; u -= row; ti++; }
    int tj = ti + u;
    int n0 = ti * 128, m0 = tj * 128;
    int z = blockIdx.y;

    const __nv_bfloat16* xh = d_xhi + (size_t)z * NP * CC_;
    const __nv_bfloat16* xl = d_xlo + (size_t)z * NP * CC_;

    // fill operand tiles (rows of 256B, swizzled 16B chunks)
    for (int idx = tid; idx < 128 * 16; idx += 256) {
        int row = idx >> 4, c16 = idx & 15;
        uint32_t off = sw_off(row, c16);
        size_t ga = (size_t)(n0 + row) * CC_ + c16 * 8;
        size_t gb = (size_t)(m0 + row) * CC_ + c16 * 8;
        *(uint4*)(sm + OFF_AHI + off) = *(const uint4*)(xh + ga);
        *(uint4*)(sm + OFF_ALO + off) = *(const uint4*)(xl + ga);
        *(uint4*)(sm + OFF_BHI + off) = *(const uint4*)(xh + gb);
        *(uint4*)(sm + OFF_BLO + off) = *(const uint4*)(xl + gb);
    }
    __syncthreads();

    float acc[2][8][4];
    #pragma unroll
    for (int i = 0; i < 2; i++)
        #pragma unroll
        for (int j = 0; j < 8; j++)
            #pragma unroll
            for (int q = 0; q < 4; q++) acc[i][j][q] = 0.f;

    const uint32_t aoff[3] = { OFF_AHI, OFF_AHI, OFF_ALO };
    const uint32_t boff[3] = { OFF_BHI, OFF_BLO, OFF_BHI };

    int a_row_lo = (lane & 15), a_half = lane >> 4;
    int b_row_lo = (lane & 7) + ((lane >> 4) << 3);
    int b_half = (lane >> 3) & 1;

    #pragma unroll
    for (int t = 0; t < 3; t++) {
        uint32_t abase = smem_base + aoff[t];
        uint32_t bbase = smem_base + boff[t];
        #pragma unroll
        for (int kc = 0; kc < 8; kc++) {
            uint32_t a[2][4];
            #pragma unroll
            for (int mi = 0; mi < 2; mi++) {
                int row = wm * 32 + mi * 16 + a_row_lo;
                LDSM_X4(a[mi], abase + sw_off(row, 2 * kc + a_half));
            }
            uint32_t bf[4][4];
            #pragma unroll
            for (int ni16 = 0; ni16 < 4; ni16++) {
                int row = wn * 64 + ni16 * 16 + b_row_lo;
                LDSM_X4(bf[ni16], bbase + sw_off(row, 2 * kc + b_half));
            }
            #pragma unroll
            for (int mi = 0; mi < 2; mi++)
                #pragma unroll
                for (int ni = 0; ni < 8; ni++)
                    MMA16816(acc[mi][ni], a[mi], (&bf[ni >> 1][(ni & 1) * 2]));
        }
    }
    __syncthreads();   // operands dead; reuse smem as fp32 stage

    float* stage = (float*)sm;
    int r_base = wm * 32 + (lane >> 2);
    int c_base = wn * 64 + 2 * (lane & 3);
    #pragma unroll
    for (int mi = 0; mi < 2; mi++)
        #pragma unroll
        for (int ni = 0; ni < 8; ni++) {
            float* p = stage + (size_t)(r_base + mi * 16) * STG_LD + c_base + ni * 8;
            p[0] = acc[mi][ni][0];
            p[1] = acc[mi][ni][1];
            p[8 * STG_LD] = acc[mi][ni][2];
            p[8 * STG_LD + 1] = acc[mi][ni][3];
        }
    __syncthreads();

    float* Cz = d_corr + (size_t)z * NP * NP;
    for (int idx = tid; idx < 128 * 32; idx += 256) {
        int row = idx >> 5, colb = (idx & 31) * 4;
        float4 v = *(float4*)(stage + row * STG_LD + colb);
        *(float4*)(Cz + (size_t)(n0 + row) * NP + m0 + colb) = v;
    }
    if (ti != tj) {
        for (int idx = tid; idx < 128 * 32; idx += 256) {
            int mrow = idx >> 5, ncb = (idx & 31) * 4;
            float4 v = make_float4(stage[(ncb + 0) * STG_LD + mrow],
                                   stage[(ncb + 1) * STG_LD + mrow],
                                   stage[(ncb + 2) * STG_LD + mrow],
                                   stage[(ncb + 3) * STG_LD + mrow]);
            *(float4*)(Cz + (size_t)(m0 + mrow) * NP + n0 + ncb) = v;
        }
    }
}

// ================= K3: per-row sums of exp(a), float4 ========================
__global__ void __launch_bounds__(256) k3_rowsum(const float* __restrict__ alphap) {
    __shared__ float er[NPH];
    int tid = threadIdx.x;
    if (tid < NPH) er[tid] = expf(-(float)(tid * tid) / 5.12f);
    __syncthreads();
    float alpha = *alphap;
    int b = blockIdx.x >> 7;
    int rowblk = blockIdx.x & 127;
    int warp = tid >> 5, lane = tid & 31;
    int n = rowblk * 8 + warp;
    int rn = n >> 5, cn = n & 31;
    const float4* r0 = (const float4*)(d_corr + ((size_t)(b * 2 + 0) * NP + n) * NP);
    const float4* r1 = (const float4*)(d_corr + ((size_t)(b * 2 + 1) * NP + n) * NP);
    int cmb = (lane & 7) * 4;
    float ec0 = alpha * er[abs(cn - (cmb + 0))];
    float ec1 = alpha * er[abs(cn - (cmb + 1))];
    float ec2 = alpha * er[abs(cn - (cmb + 2))];
    float ec3 = alpha * er[abs(cn - (cmb + 3))];
    int rmb = lane >> 3;
    float s0 = 0.f, s1 = 0.f, s2 = 0.f;
    #pragma unroll
    for (int i = 0; i < 8; i++) {
        float4 v0 = r0[i * 32 + lane];
        float4 v1 = r1[i * 32 + lane];
        float erow = er[abs(rn - (i * 4 + rmb))];
        float f0 = alpha - erow * ec0;
        float f1 = alpha - erow * ec1;
        float f2 = alpha - erow * ec2;
        float f3 = alpha - erow * ec3;
        s0 += __expf(v0.x * f0) + __expf(v0.y * f1) + __expf(v0.z * f2) + __expf(v0.w * f3);
        s1 += __expf(v1.x * f0) + __expf(v1.y * f1) + __expf(v1.z * f2) + __expf(v1.w * f3);
        s2 += __expf((v0.x + v1.x) * 0.5f * f0) + __expf((v0.y + v1.y) * 0.5f * f1) +
              __expf((v0.z + v1.z) * 0.5f * f2) + __expf((v0.w + v1.w) * 0.5f * f3);
    }
    #pragma unroll
    for (int off = 16; off; off >>= 1) {
        s0 += __shfl_xor_sync(0xffffffffu, s0, off);
        s1 += __shfl_xor_sync(0xffffffffu, s1, off);
        s2 += __shfl_xor_sync(0xffffffffu, s2, off);
    }
    if (lane == 0) {
        d_inv[(b * 3 + 0) * NP + n] = 1.0f / s0;
        d_inv[(b * 3 + 1) * NP + n] = 1.0f / s1;
        d_inv[(b * 3 + 2) * NP + n] = 1.0f / s2;
    }
}

// ---- top-3 helpers ----
__device__ __forceinline__ void ins3(float v, float& t0, float& t1, float& t2) {
    if (v > t2) {
        if (v > t1) {
            t2 = t1;
            if (v > t0) { t1 = t0; t0 = v; }
            else t1 = v;
        } else t2 = v;
    }
}
__device__ __forceinline__ void merge3(float& a0, float& a1, float& a2,
                                       float b0, float b1, float b2) {
    float mx0 = fmaxf(a0, b0), mn0 = fminf(a0, b0);
    float mx1 = fmaxf(a1, b1);
    float mx2 = fmaxf(a2, b2);
    a0 = mx0;
    a1 = fmaxf(mn0, mx1);
    a2 = fmaxf(fminf(mn0, mx1), mx2);
}

// ================= K4: S, top-3 per row, scatter (float4) ====================
__global__ void __launch_bounds__(256) k4_final(const float* __restrict__ alphap,
                                                float* __restrict__ out) {
    __shared__ float er_s[NPH];
    __shared__ float inv_s[3][NP];
    int tid = threadIdx.x;
    int b = blockIdx.x >> 7;
    int rowblk = blockIdx.x & 127;
    if (tid < NPH) er_s[tid] = expf(-(float)(tid * tid) / 5.12f);
    for (int idx = tid; idx < 3 * NP; idx += 256)
        ((float*)inv_s)[idx] = d_inv[b * 3 * NP + idx];
    __syncthreads();

    float alpha = *alphap;
    int warp = tid >> 5, lane = tid & 31;
    int n = rowblk * 8 + warp;
    int rn = n >> 5, cn = n & 31;
    const float4* r0 = (const float4*)(d_corr + ((size_t)(b * 2) * NP + n) * NP);
    const float4* r1 = (const float4*)((const float*)r0 + (size_t)NP * NP);
    int cmb = (lane & 7) * 4;
    float ec[4];
    #pragma unroll
    for (int q = 0; q < 4; q++) ec[q] = alpha * er_s[abs(cn - (cmb + q))];
    int rmb = lane >> 3;

    float t00 = 0.f, t01 = 0.f, t02 = 0.f;
    float t10 = 0.f, t11 = 0.f, t12 = 0.f;
    float t20 = 0.f, t21 = 0.f, t22 = 0.f;

    #pragma unroll
    for (int i = 0; i < 8; i++) {
        float4 v0 = r0[i * 32 + lane];
        float4 v1 = r1[i * 32 + lane];
        float erow = er_s[abs(rn - (i * 4 + rmb))];
        int mbase = i * 128 + lane * 4;
        float a0[4] = { v0.x, v0.y, v0.z, v0.w };
        float a1[4] = { v1.x, v1.y, v1.z, v1.w };
        #pragma unroll
        for (int q = 0; q < 4; q++) {
            float f = alpha - erow * ec[q];
            float e0 = __expf(a0[q] * f);
            float e1 = __expf(a1[q] * f);
            int m = mbase + q;
            ins3(e0 * e0 * inv_s[0][m], t00, t01, t02);
            ins3(e1 * e1 * inv_s[1][m], t10, t11, t12);
            ins3(e0 * e1 * inv_s[2][m], t20, t21, t22);
        }
    }
    #pragma unroll
    for (int off = 16; off; off >>= 1) {
        float b0, b1, b2;
        b0 = __shfl_xor_sync(0xffffffffu, t00, off);
        b1 = __shfl_xor_sync(0xffffffffu, t01, off);
        b2 = __shfl_xor_sync(0xffffffffu, t02, off);
        merge3(t00, t01, t02, b0, b1, b2);
        b0 = __shfl_xor_sync(0xffffffffu, t10, off);
        b1 = __shfl_xor_sync(0xffffffffu, t11, off);
        b2 = __shfl_xor_sync(0xffffffffu, t12, off);
        merge3(t10, t11, t12, b0, b1, b2);
        b0 = __shfl_xor_sync(0xffffffffu, t20, off);
        b1 = __shfl_xor_sync(0xffffffffu, t21, off);
        b2 = __shfl_xor_sync(0xffffffffu, t22, off);
        merge3(t20, t21, t22, b0, b1, b2);
    }
    if (lane < 12) {
        int k = lane >> 2, pix = lane & 3;
        int chn = (pix == 0) ? 0 : ((pix == 3) ? 1 : 2);
        float a0 = (chn == 0) ? t00 : (chn == 1) ? t10 : t20;
        float a1 = (chn == 0) ? t01 : (chn == 1) ? t11 : t21;
        float a2 = (chn == 0) ? t02 : (chn == 1) ? t12 : t22;
        float val = (k == 0) ? a0 : (k == 1) ? a1 : a2;
        val *= inv_s[chn][n];
        int hh = 2 * rn + (pix >> 1);
        int ww = 2 * cn + (pix & 1);
        out[(((size_t)b * 3 + k) * HH + hh) * WW + ww] = val;
    }
}

// ================= launch ====================================================
extern "C" void kernel_launch(void* const* d_in, const int* in_sizes, int n_in,
                              void* d_out, int out_size) {
    const float* x = (const float*)d_in[0];
    const float* alpha = (const float*)d_in[1];
    float* out = (float*)d_out;

    static int configured = 0;
    if (!configured) {
        cudaFuncSetAttribute(k2_gemm, cudaFuncAttributeMaxDynamicSharedMemorySize,
                             K2_SMEM);
        configured = 1;
    }

    k1_norm<<<dim3(HH, BB), 256>>>(x);
    k2_gemm<<<dim3(36, 16), 256, K2_SMEM>>>();
    k3_rowsum<<<1024, 256>>>(alpha);
    k4_final<<<1024, 256>>>(alpha, out);
}

// round 5
// speedup vs baseline: 2.0637x; 1.1900x over previous
#include <cuda_runtime.h>
#include <cuda_bf16.h>
#include <cstdint>
#include <math.h>

#define BB 8
#define CC_ 128
#define HH 64
#define WW 64
#define NPH 32
#define NP 1024

typedef unsigned long long u64;

// ---------------- scratch (device globals; no allocs allowed) ----------------
__device__ __nv_bfloat16 d_xhi[16 * NP * CC_];          // [z][n][c] 4 MB
__device__ __nv_bfloat16 d_xlo[16 * NP * CC_];          // [z][n][c] 4 MB
__device__ float d_E[(size_t)16 * NP * NP];             // [z][n][m] E=exp(a*f) 64 MB
__device__ float d_inv[BB * 3 * NP];                    // [b][ch][n]

// ---------------- baseline-PTX tensor core helpers (sm_80+) ----------------
__device__ __forceinline__ uint32_t smem_to_u32(const void* p) {
    uint32_t a;
    asm("{ .reg .u64 t; cvta.to.shared.u64 t, %1; cvt.u32.u64 %0, t; }"
        : "=r"(a) : "l"(p));
    return a;
}
#define LDSM_X4(r, addr) \
    asm volatile("ldmatrix.sync.aligned.m8n8.x4.shared.b16 {%0,%1,%2,%3}, [%4];" \
        : "=r"((r)[0]), "=r"((r)[1]), "=r"((r)[2]), "=r"((r)[3]) : "r"(addr))
#define MMA16816(c, a, b) \
    asm volatile("mma.sync.aligned.m16n8k16.row.col.f32.bf16.bf16.f32 " \
        "{%0,%1,%2,%3}, {%4,%5,%6,%7}, {%8,%9}, {%0,%1,%2,%3};" \
        : "+f"((c)[0]), "+f"((c)[1]), "+f"((c)[2]), "+f"((c)[3]) \
        : "r"((a)[0]), "r"((a)[1]), "r"((a)[2]), "r"((a)[3]), \
          "r"((b)[0]), "r"((b)[1]))

// swizzled smem byte offset for bf16 tile [128 rows][8 x 16B chunks] (128B rows)
__device__ __forceinline__ uint32_t sw64(int row, int c16) {
    return (uint32_t)((row << 7) | (((c16) ^ (row & 7)) << 4));
}

// ================= K1: L2-normalize over C, extract diag pixels, bf16 split =
__global__ void __launch_bounds__(256) k1_norm(const float* __restrict__ x) {
    __shared__ float xs[CC_ * 65];
    __shared__ float ssp[4][WW];
    __shared__ float invn[WW];
    int b = blockIdx.y, h = blockIdx.x;
    int tid = threadIdx.x;
    const float* xrow = x + (size_t)b * CC_ * HH * WW + (size_t)h * WW;
    for (int idx = tid; idx < CC_ * WW; idx += 256) {
        int c = idx >> 6, w = idx & 63;
        xs[c * 65 + w] = xrow[(size_t)c * HH * WW + w];
    }
    __syncthreads();
    {
        int w = tid & 63, c4 = tid >> 6;
        float ss = 0.f;
        #pragma unroll 8
        for (int c = c4 * 32; c < c4 * 32 + 32; c++) {
            float v = xs[c * 65 + w];
            ss += v * v;
        }
        ssp[c4][w] = ss;
    }
    __syncthreads();
    if (tid < WW) {
        float s = ssp[0][tid] + ssp[1][tid] + ssp[2][tid] + ssp[3][tid];
        invn[tid] = 1.0f / fmaxf(sqrtf(s), 1e-12f);
    }
    __syncthreads();
    int p = h & 1;
    int z = b * 2 + p;
    int nb = (h >> 1) * NPH;
    for (int idx = tid; idx < NPH * CC_; idx += 256) {
        int j = idx >> 7, c = idx & 127;
        int w = 2 * j + p;
        float v = xs[c * 65 + w] * invn[w];
        __nv_bfloat16 hi = __float2bfloat16(v);
        float lo = v - __bfloat162float(hi);
        size_t o = ((size_t)z * NP + nb + j) * CC_ + c;
        d_xhi[o] = hi;
        d_xlo[o] = __float2bfloat16(lo);
    }
}

// ================= K2: bf16 split Gram GEMM + fused exp(mask) epilogue ======
// E[z][n][m] = exp(corr * alpha*(1-mask)); triangle tiles, stores normal+T.
#define OP_AHI 0
#define OP_ALO 16384
#define OP_BHI 32768
#define OP_BLO 49152
#define STG_LD 129
#define ER_OFF 66048
#define K2_SMEM 66304

__global__ void __launch_bounds__(256, 2) k2_gemm(const float* __restrict__ alphap) {
    extern __shared__ char sm[];
    uint32_t smem_base = smem_to_u32(sm);
    int tid = threadIdx.x;
    int wid = tid >> 5, lane = tid & 31;
    int wm = wid & 3, wn = wid >> 2;
    float* er = (float*)(sm + ER_OFF);
    if (tid < 32) er[tid] = expf(-(float)(tid * tid) / 5.12f);

    // triangle tile decode
    int u = blockIdx.x, ti = 0;
    for (;;) { int row = 8 - ti; if (u < row) break; u -= row; ti++; }
    int tj = ti + u;
    int n0 = ti * 128, m0 = tj * 128;
    int z = blockIdx.y;

    const __nv_bfloat16* xh = d_xhi + (size_t)z * NP * CC_;
    const __nv_bfloat16* xl = d_xlo + (size_t)z * NP * CC_;

    float acc[2][8][4];
    #pragma unroll
    for (int i = 0; i < 2; i++)
        #pragma unroll
        for (int j = 0; j < 8; j++)
            #pragma unroll
            for (int q = 0; q < 4; q++) acc[i][j][q] = 0.f;

    int a_row_lo = (lane & 15), a_half = lane >> 4;
    int b_row_lo = (lane & 7) + ((lane >> 4) << 3);
    int b_half = (lane >> 3) & 1;

    for (int kk = 0; kk < CC_; kk += 64) {
        // load 4 operand tiles [128 x 64] bf16 each
        for (int idx = tid; idx < 1024; idx += 256) {
            int row = idx >> 3, c16 = idx & 7;
            uint32_t off = sw64(row, c16);
            size_t ga = (size_t)(n0 + row) * CC_ + kk + c16 * 8;
            size_t gb = (size_t)(m0 + row) * CC_ + kk + c16 * 8;
            *(uint4*)(sm + OP_AHI + off) = *(const uint4*)(xh + ga);
            *(uint4*)(sm + OP_ALO + off) = *(const uint4*)(xl + ga);
            *(uint4*)(sm + OP_BHI + off) = *(const uint4*)(xh + gb);
            *(uint4*)(sm + OP_BLO + off) = *(const uint4*)(xl + gb);
        }
        __syncthreads();
        const uint32_t aoff[3] = { OP_AHI, OP_AHI, OP_ALO };
        const uint32_t boff[3] = { OP_BHI, OP_BLO, OP_BHI };
        #pragma unroll
        for (int t = 0; t < 3; t++) {
            uint32_t abase = smem_base + aoff[t];
            uint32_t bbase = smem_base + boff[t];
            #pragma unroll
            for (int kc = 0; kc < 4; kc++) {
                uint32_t a[2][4];
                #pragma unroll
                for (int mi = 0; mi < 2; mi++) {
                    int row = wm * 32 + mi * 16 + a_row_lo;
                    LDSM_X4(a[mi], abase + sw64(row, 2 * kc + a_half));
                }
                uint32_t bf[4][4];
                #pragma unroll
                for (int ni16 = 0; ni16 < 4; ni16++) {
                    int row = wn * 64 + ni16 * 16 + b_row_lo;
                    LDSM_X4(bf[ni16], bbase + sw64(row, 2 * kc + b_half));
                }
                #pragma unroll
                for (int mi = 0; mi < 2; mi++)
                    #pragma unroll
                    for (int ni = 0; ni < 8; ni++)
                        MMA16816(acc[mi][ni], a[mi], (&bf[ni >> 1][(ni & 1) * 2]));
            }
        }
        __syncthreads();
    }

    // epilogue: E = exp(v * alpha*(1-mask)) into stage (LD=129), then store
    float alpha = __ldg(alphap);
    float* stage = (float*)sm;
    int r_base = wm * 32 + (lane >> 2);
    int c_base = wn * 64 + 2 * (lane & 3);
    #pragma unroll
    for (int mi = 0; mi < 2; mi++)
        #pragma unroll
        for (int ni = 0; ni < 8; ni++)
            #pragma unroll
            for (int q = 0; q < 4; q++) {
                int r = r_base + mi * 16 + (q >> 1) * 8;
                int c = c_base + ni * 8 + (q & 1);
                int n = n0 + r, m = m0 + c;
                float g = er[abs((n >> 5) - (m >> 5))] * er[abs((n & 31) - (m & 31))];
                stage[r * STG_LD + c] = __expf(acc[mi][ni][q] * (alpha * (1.0f - g)));
            }
    __syncthreads();

    float* Ez = d_E + (size_t)z * NP * NP;
    for (int idx = tid; idx < 128 * 128; idx += 256) {
        int row = idx >> 7, col = idx & 127;
        Ez[(size_t)(n0 + row) * NP + m0 + col] = stage[row * STG_LD + col];
    }
    if (ti != tj) {
        for (int idx = tid; idx < 128 * 128; idx += 256) {
            int mrow = idx >> 7, nc = idx & 127;
            Ez[(size_t)(m0 + mrow) * NP + n0 + nc] = stage[nc * STG_LD + mrow];
        }
    }
}

// ================= K3: pure row sums of E (2 warps/row) =====================
__global__ void __launch_bounds__(256) k3_rowsum() {
    __shared__ float part[8][3];
    int tid = threadIdx.x, wid = tid >> 5, lane = tid & 31;
    int blk = blockIdx.x;             // 2048 = 8 b x 256
    int b = blk >> 8;
    int rl = wid >> 1, half = wid & 1;
    int n = (blk & 255) * 4 + rl;
    const float4* e0p = (const float4*)(d_E + ((size_t)(b * 2) * NP + n) * NP) + half * 128;
    const float4* e1p = e0p + (size_t)NP * NP / 4;
    float s0 = 0.f, s1 = 0.f, s2 = 0.f;
    #pragma unroll
    for (int i = 0; i < 4; i++) {
        float4 e0 = e0p[i * 32 + lane];
        float4 e1 = e1p[i * 32 + lane];
        s0 += (e0.x + e0.y) + (e0.z + e0.w);
        s1 += (e1.x + e1.y) + (e1.z + e1.w);
        float p;
        p = e0.x * e1.x; s2 += p * rsqrtf(p);
        p = e0.y * e1.y; s2 += p * rsqrtf(p);
        p = e0.z * e1.z; s2 += p * rsqrtf(p);
        p = e0.w * e1.w; s2 += p * rsqrtf(p);
    }
    #pragma unroll
    for (int off = 16; off; off >>= 1) {
        s0 += __shfl_xor_sync(0xffffffffu, s0, off);
        s1 += __shfl_xor_sync(0xffffffffu, s1, off);
        s2 += __shfl_xor_sync(0xffffffffu, s2, off);
    }
    if (lane == 0) { part[wid][0] = s0; part[wid][1] = s1; part[wid][2] = s2; }
    __syncthreads();
    if (tid < 12) {
        int rl2 = tid / 3, ch = tid % 3;
        float s = part[2 * rl2][ch] + part[2 * rl2 + 1][ch];
        int nn = (blk & 255) * 4 + rl2;
        d_inv[(b * 3 + ch) * NP + nn] = 1.0f / s;
    }
}

// ---- top-3 helpers ----
__device__ __forceinline__ void ins3(float v, float& t0, float& t1, float& t2) {
    if (v > t2) {
        if (v > t1) {
            t2 = t1;
            if (v > t0) { t1 = t0; t0 = v; }
            else t1 = v;
        } else t2 = v;
    }
}
__device__ __forceinline__ void merge3(float& a0, float& a1, float& a2,
                                       float b0, float b1, float b2) {
    float mx0 = fmaxf(a0, b0), mn0 = fminf(a0, b0);
    float mx1 = fmaxf(a1, b1);
    float mx2 = fmaxf(a2, b2);
    a0 = mx0;
    a1 = fmaxf(mn0, mx1);
    a2 = fmaxf(fminf(mn0, mx1), mx2);
}

// ================= K4: S = E^2*inv*inv top-3 per row, scatter (2 warps/row) ==
__global__ void __launch_bounds__(256) k4_final(float* __restrict__ out) {
    __shared__ __align__(16) float inv_s[3][NP];
    __shared__ float wpart[8][9];
    int tid = threadIdx.x, wid = tid >> 5, lane = tid & 31;
    int blk = blockIdx.x;             // 2048
    int b = blk >> 8;
    for (int idx = tid; idx < 3 * NP; idx += 256)
        ((float*)inv_s)[idx] = d_inv[b * 3 * NP + idx];
    __syncthreads();

    int rl = wid >> 1, half = wid & 1;
    int n = (blk & 255) * 4 + rl;
    const float4* e0p = (const float4*)(d_E + ((size_t)(b * 2) * NP + n) * NP) + half * 128;
    const float4* e1p = e0p + (size_t)NP * NP / 4;

    float tA[9], tB[9];
    #pragma unroll
    for (int j = 0; j < 9; j++) { tA[j] = 0.f; tB[j] = 0.f; }

    #pragma unroll
    for (int i = 0; i < 4; i++) {
        int m4 = half * 128 + i * 32 + lane;
        float4 e0 = e0p[i * 32 + lane];
        float4 e1 = e1p[i * 32 + lane];
        float4 i0 = ((const float4*)inv_s[0])[m4];
        float4 i1 = ((const float4*)inv_s[1])[m4];
        float4 i2 = ((const float4*)inv_s[2])[m4];
        #define PROC(T) do { \
            ins3(e0.x * e0.x * i0.x, T[0], T[1], T[2]); \
            ins3(e0.y * e0.y * i0.y, T[0], T[1], T[2]); \
            ins3(e0.z * e0.z * i0.z, T[0], T[1], T[2]); \
            ins3(e0.w * e0.w * i0.w, T[0], T[1], T[2]); \
            ins3(e1.x * e1.x * i1.x, T[3], T[4], T[5]); \
            ins3(e1.y * e1.y * i1.y, T[3], T[4], T[5]); \
            ins3(e1.z * e1.z * i1.z, T[3], T[4], T[5]); \
            ins3(e1.w * e1.w * i1.w, T[3], T[4], T[5]); \
            ins3(e0.x * e1.x * i2.x, T[6], T[7], T[8]); \
            ins3(e0.y * e1.y * i2.y, T[6], T[7], T[8]); \
            ins3(e0.z * e1.z * i2.z, T[6], T[7], T[8]); \
            ins3(e0.w * e1.w * i2.w, T[6], T[7], T[8]); \
        } while (0)
        if (i & 1) PROC(tB); else PROC(tA);
        #undef PROC
    }
    #pragma unroll
    for (int ch = 0; ch < 3; ch++)
        merge3(tA[ch * 3], tA[ch * 3 + 1], tA[ch * 3 + 2],
               tB[ch * 3], tB[ch * 3 + 1], tB[ch * 3 + 2]);
    #pragma unroll
    for (int off = 16; off; off >>= 1) {
        #pragma unroll
        for (int ch = 0; ch < 3; ch++) {
            float b0 = __shfl_xor_sync(0xffffffffu, tA[ch * 3], off);
            float b1 = __shfl_xor_sync(0xffffffffu, tA[ch * 3 + 1], off);
            float b2 = __shfl_xor_sync(0xffffffffu, tA[ch * 3 + 2], off);
            merge3(tA[ch * 3], tA[ch * 3 + 1], tA[ch * 3 + 2], b0, b1, b2);
        }
    }
    if (lane < 9) {
        float v = tA[0];
        #pragma unroll
        for (int j = 1; j < 9; j++) v = (lane == j) ? tA[j] : v;
        wpart[wid][lane] = v;
    }
    __syncthreads();
    if (tid < 48) {
        int rl2 = tid / 12, j = tid % 12;
        int k = j >> 2, pix = j & 3;
        int chn = (pix == 0) ? 0 : ((pix == 3) ? 1 : 2);
        int w0 = rl2 * 2;
        float a0 = wpart[w0][chn * 3], a1 = wpart[w0][chn * 3 + 1], a2 = wpart[w0][chn * 3 + 2];
        merge3(a0, a1, a2, wpart[w0 + 1][chn * 3], wpart[w0 + 1][chn * 3 + 1],
               wpart[w0 + 1][chn * 3 + 2]);
        float val = (k == 0) ? a0 : (k == 1) ? a1 : a2;
        int nn = (blk & 255) * 4 + rl2;
        val *= inv_s[chn][nn];
        int rn = nn >> 5, cn = nn & 31;
        int hh = 2 * rn + (pix >> 1), ww = 2 * cn + (pix & 1);
        out[(((size_t)b * 3 + k) * HH + hh) * WW + ww] = val;
    }
}

// ================= launch ====================================================
extern "C" void kernel_launch(void* const* d_in, const int* in_sizes, int n_in,
                              void* d_out, int out_size) {
    const float* x = (const float*)d_in[0];
    const float* alpha = (const float*)d_in[1];
    float* out = (float*)d_out;

    cudaFuncSetAttribute(k2_gemm, cudaFuncAttributeMaxDynamicSharedMemorySize,
                         K2_SMEM);

    k1_norm<<<dim3(HH, BB), 256>>>(x);
    k2_gemm<<<dim3(36, 16), 256, K2_SMEM>>>(alpha);
    k3_rowsum<<<2048, 256>>>();
    k4_final<<<2048, 256>>>(out);
}

// round 7
// speedup vs baseline: 2.2331x; 1.0821x over previous
#include <cuda_runtime.h>
#include <cuda_bf16.h>
#include <cstdint>
#include <math.h>

#define BB 8
#define CC_ 128
#define HH 64
#define WW 64
#define NPH 32
#define NP 1024

typedef unsigned long long u64;

// ---------------- scratch (device globals; no allocs allowed) ----------------
__device__ __nv_bfloat16 d_xhi[16 * NP * CC_];          // [z][n][c] 4 MB
__device__ __nv_bfloat16 d_xlo[16 * NP * CC_];          // [z][n][c] 4 MB
__device__ float d_E[(size_t)16 * NP * NP];             // [z][n][m] E=exp(a*f) 64 MB
__device__ float d_inv[BB * 3 * NP];                    // [b][ch][n]

// ---------------- baseline-PTX tensor core helpers (sm_80+) ----------------
__device__ __forceinline__ uint32_t smem_to_u32(const void* p) {
    uint32_t a;
    asm("{ .reg .u64 t; cvta.to.shared.u64 t, %1; cvt.u32.u64 %0, t; }"
        : "=r"(a) : "l"(p));
    return a;
}
#define LDSM_X4(r, addr) \
    asm volatile("ldmatrix.sync.aligned.m8n8.x4.shared.b16 {%0,%1,%2,%3}, [%4];" \
        : "=r"((r)[0]), "=r"((r)[1]), "=r"((r)[2]), "=r"((r)[3]) : "r"(addr))
#define MMA16816(c, a, b) \
    asm volatile("mma.sync.aligned.m16n8k16.row.col.f32.bf16.bf16.f32 " \
        "{%0,%1,%2,%3}, {%4,%5,%6,%7}, {%8,%9}, {%0,%1,%2,%3};" \
        : "+f"((c)[0]), "+f"((c)[1]), "+f"((c)[2]), "+f"((c)[3]) \
        : "r"((a)[0]), "r"((a)[1]), "r"((a)[2]), "r"((a)[3]), \
          "r"((b)[0]), "r"((b)[1]))

// swizzled smem byte offset for bf16 tile [128 rows][8 x 16B chunks] (128B rows)
__device__ __forceinline__ uint32_t sw64(int row, int c16) {
    return (uint32_t)((row << 7) | (((c16) ^ (row & 7)) << 4));
}

// ================= K1: L2-normalize over C, extract diag pixels, bf16 split =
__global__ void __launch_bounds__(256) k1_norm(const float* __restrict__ x) {
    __shared__ float xs[CC_ * 65];
    __shared__ float ssp[4][WW];
    __shared__ float invn[WW];
    int b = blockIdx.y, h = blockIdx.x;
    int tid = threadIdx.x;
    const float* xrow = x + (size_t)b * CC_ * HH * WW + (size_t)h * WW;
    for (int idx = tid; idx < CC_ * WW; idx += 256) {
        int c = idx >> 6, w = idx & 63;
        xs[c * 65 + w] = xrow[(size_t)c * HH * WW + w];
    }
    __syncthreads();
    {
        int w = tid & 63, c4 = tid >> 6;
        float ss = 0.f;
        #pragma unroll 8
        for (int c = c4 * 32; c < c4 * 32 + 32; c++) {
            float v = xs[c * 65 + w];
            ss += v * v;
        }
        ssp[c4][w] = ss;
    }
    __syncthreads();
    if (tid < WW) {
        float s = ssp[0][tid] + ssp[1][tid] + ssp[2][tid] + ssp[3][tid];
        invn[tid] = 1.0f / fmaxf(sqrtf(s), 1e-12f);
    }
    __syncthreads();
    int p = h & 1;
    int z = b * 2 + p;
    int nb = (h >> 1) * NPH;
    for (int idx = tid; idx < NPH * CC_; idx += 256) {
        int j = idx >> 7, c = idx & 127;
        int w = 2 * j + p;
        float v = xs[c * 65 + w] * invn[w];
        __nv_bfloat16 hi = __float2bfloat16(v);
        float lo = v - __bfloat162float(hi);
        size_t o = ((size_t)z * NP + nb + j) * CC_ + c;
        d_xhi[o] = hi;
        d_xlo[o] = __float2bfloat16(lo);
    }
}

// ================= K2: bf16 split Gram GEMM + fused exp(mask) epilogue ======
// E[z][n][m] = exp(corr * alpha*(1-mask)); triangle tiles, stores normal+T.
#define OP_AHI 0
#define OP_ALO 16384
#define OP_BHI 32768
#define OP_BLO 49152
#define STG_LD 129
#define ER_OFF 66048
#define K2_SMEM 66304

__global__ void __launch_bounds__(256, 2) k2_gemm(const float* __restrict__ alphap) {
    extern __shared__ char sm[];
    uint32_t smem_base = smem_to_u32(sm);
    int tid = threadIdx.x;
    int wid = tid >> 5, lane = tid & 31;
    int wm = wid & 3, wn = wid >> 2;
    float* er = (float*)(sm + ER_OFF);
    if (tid < 32) er[tid] = expf(-(float)(tid * tid) / 5.12f);

    // triangle tile decode
    int u = blockIdx.x, ti = 0;
    for (;;) { int row = 8 - ti; if (u < row) break; u -= row; ti++; }
    int tj = ti + u;
    int n0 = ti * 128, m0 = tj * 128;
    int z = blockIdx.y;

    const __nv_bfloat16* xh = d_xhi + (size_t)z * NP * CC_;
    const __nv_bfloat16* xl = d_xlo + (size_t)z * NP * CC_;

    float acc[2][8][4];
    #pragma unroll
    for (int i = 0; i < 2; i++)
        #pragma unroll
        for (int j = 0; j < 8; j++)
            #pragma unroll
            for (int q = 0; q < 4; q++) acc[i][j][q] = 0.f;

    int a_row_lo = (lane & 15), a_half = lane >> 4;
    int b_row_lo = (lane & 7) + ((lane >> 4) << 3);
    int b_half = (lane >> 3) & 1;

    for (int kk = 0; kk < CC_; kk += 64) {
        // load 4 operand tiles [128 x 64] bf16 each
        for (int idx = tid; idx < 1024; idx += 256) {
            int row = idx >> 3, c16 = idx & 7;
            uint32_t off = sw64(row, c16);
            size_t ga = (size_t)(n0 + row) * CC_ + kk + c16 * 8;
            size_t gb = (size_t)(m0 + row) * CC_ + kk + c16 * 8;
            *(uint4*)(sm + OP_AHI + off) = *(const uint4*)(xh + ga);
            *(uint4*)(sm + OP_ALO + off) = *(const uint4*)(xl + ga);
            *(uint4*)(sm + OP_BHI + off) = *(const uint4*)(xh + gb);
            *(uint4*)(sm + OP_BLO + off) = *(const uint4*)(xl + gb);
        }
        __syncthreads();
        const uint32_t aoff[3] = { OP_AHI, OP_AHI, OP_ALO };
        const uint32_t boff[3] = { OP_BHI, OP_BLO, OP_BHI };
        #pragma unroll
        for (int t = 0; t < 3; t++) {
            uint32_t abase = smem_base + aoff[t];
            uint32_t bbase = smem_base + boff[t];
            #pragma unroll
            for (int kc = 0; kc < 4; kc++) {
                uint32_t a[2][4];
                #pragma unroll
                for (int mi = 0; mi < 2; mi++) {
                    int row = wm * 32 + mi * 16 + a_row_lo;
                    LDSM_X4(a[mi], abase + sw64(row, 2 * kc + a_half));
                }
                uint32_t bf[4][4];
                #pragma unroll
                for (int ni16 = 0; ni16 < 4; ni16++) {
                    int row = wn * 64 + ni16 * 16 + b_row_lo;
                    LDSM_X4(bf[ni16], bbase + sw64(row, 2 * kc + b_half));
                }
                #pragma unroll
                for (int mi = 0; mi < 2; mi++)
                    #pragma unroll
                    for (int ni = 0; ni < 8; ni++)
                        MMA16816(acc[mi][ni], a[mi], (&bf[ni >> 1][(ni & 1) * 2]));
            }
        }
        __syncthreads();
    }

    // epilogue: E = exp(v * alpha*(1-mask)) into stage (LD=129), then store
    float alpha = __ldg(alphap);
    float* stage = (float*)sm;
    int r_base = wm * 32 + (lane >> 2);
    int c_base = wn * 64 + 2 * (lane & 3);
    #pragma unroll
    for (int mi = 0; mi < 2; mi++)
        #pragma unroll
        for (int ni = 0; ni < 8; ni++)
            #pragma unroll
            for (int q = 0; q < 4; q++) {
                int r = r_base + mi * 16 + (q >> 1) * 8;
                int c = c_base + ni * 8 + (q & 1);
                int n = n0 + r, m = m0 + c;
                float g = er[abs((n >> 5) - (m >> 5))] * er[abs((n & 31) - (m & 31))];
                stage[r * STG_LD + c] = __expf(acc[mi][ni][q] * (alpha * (1.0f - g)));
            }
    __syncthreads();

    float* Ez = d_E + (size_t)z * NP * NP;
    for (int idx = tid; idx < 128 * 128; idx += 256) {
        int row = idx >> 7, col = idx & 127;
        Ez[(size_t)(n0 + row) * NP + m0 + col] = stage[row * STG_LD + col];
    }
    if (ti != tj) {
        for (int idx = tid; idx < 128 * 128; idx += 256) {
            int mrow = idx >> 7, nc = idx & 127;
            Ez[(size_t)(m0 + mrow) * NP + n0 + nc] = stage[nc * STG_LD + mrow];
        }
    }
}

// ================= K3: pure row sums of E (2 warps/row) =====================
__global__ void __launch_bounds__(256) k3_rowsum() {
    __shared__ float part[8][3];
    int tid = threadIdx.x, wid = tid >> 5, lane = tid & 31;
    int blk = blockIdx.x;             // 2048 = 8 b x 256
    int b = blk >> 8;
    int rl = wid >> 1, half = wid & 1;
    int n = (blk & 255) * 4 + rl;
    const float4* e0p = (const float4*)(d_E + ((size_t)(b * 2) * NP + n) * NP) + half * 128;
    const float4* e1p = e0p + (size_t)NP * NP / 4;
    float s0 = 0.f, s1 = 0.f, s2 = 0.f;
    #pragma unroll
    for (int i = 0; i < 4; i++) {
        float4 e0 = e0p[i * 32 + lane];
        float4 e1 = e1p[i * 32 + lane];
        s0 += (e0.x + e0.y) + (e0.z + e0.w);
        s1 += (e1.x + e1.y) + (e1.z + e1.w);
        float p;
        p = e0.x * e1.x; s2 += p * rsqrtf(p);
        p = e0.y * e1.y; s2 += p * rsqrtf(p);
        p = e0.z * e1.z; s2 += p * rsqrtf(p);
        p = e0.w * e1.w; s2 += p * rsqrtf(p);
    }
    #pragma unroll
    for (int off = 16; off; off >>= 1) {
        s0 += __shfl_xor_sync(0xffffffffu, s0, off);
        s1 += __shfl_xor_sync(0xffffffffu, s1, off);
        s2 += __shfl_xor_sync(0xffffffffu, s2, off);
    }
    if (lane == 0) { part[wid][0] = s0; part[wid][1] = s1; part[wid][2] = s2; }
    __syncthreads();
    if (tid < 12) {
        int rl2 = tid / 3, ch = tid % 3;
        float s = part[2 * rl2][ch] + part[2 * rl2 + 1][ch];
        int nn = (blk & 255) * 4 + rl2;
        d_inv[(b * 3 + ch) * NP + nn] = 1.0f / s;
    }
}

// ---- branch-free sorted top-3 insert (t0 >= t1 >= t2, all values > 0) ----
__device__ __forceinline__ void ins3(float v, float& t0, float& t1, float& t2) {
    float lo0 = fminf(v, t0);
    t0 = fmaxf(v, t0);
    float lo1 = fminf(lo0, t1);
    t1 = fmaxf(lo0, t1);
    t2 = fmaxf(lo1, t2);
}
__device__ __forceinline__ void merge3(float& a0, float& a1, float& a2,
                                       float b0, float b1, float b2) {
    float mx0 = fmaxf(a0, b0), mn0 = fminf(a0, b0);
    float mx1 = fmaxf(a1, b1);
    float mx2 = fmaxf(a2, b2);
    a0 = mx0;
    a1 = fmaxf(mn0, mx1);
    a2 = fmaxf(fminf(mn0, mx1), mx2);
}

// ================= K4: top-3 per row on monotone keys, scatter ==============
// keys: ch0 = E0*w0[m] (w0=sqrt(inv0)), ch1 = E1*w1[m], ch2 = E0*E1*inv2[m].
// Squaring + row factors applied after selection (monotone transforms).
__global__ void __launch_bounds__(256) k4_final(float* __restrict__ out) {
    __shared__ __align__(16) float w0s[NP];
    __shared__ __align__(16) float w1s[NP];
    __shared__ __align__(16) float i2s[NP];
    __shared__ float wpart[8][9];
    int tid = threadIdx.x, wid = tid >> 5, lane = tid & 31;
    int blk = blockIdx.x;             // 2048
    int b = blk >> 8;
    for (int idx = tid; idx < NP; idx += 256) {
        float i0 = d_inv[(b * 3 + 0) * NP + idx];
        float i1 = d_inv[(b * 3 + 1) * NP + idx];
        w0s[idx] = sqrtf(i0);
        w1s[idx] = sqrtf(i1);
        i2s[idx] = d_inv[(b * 3 + 2) * NP + idx];
    }
    __syncthreads();

    int rl = wid >> 1, half = wid & 1;
    int n = (blk & 255) * 4 + rl;
    const float4* e0p = (const float4*)(d_E + ((size_t)(b * 2) * NP + n) * NP) + half * 128;
    const float4* e1p = e0p + (size_t)NP * NP / 4;

    float t[9];
    #pragma unroll
    for (int j = 0; j < 9; j++) t[j] = 0.f;

    #pragma unroll
    for (int i = 0; i < 4; i++) {
        int m4 = half * 128 + i * 32 + lane;    // float4 index into [0,256)
        float4 e0 = e0p[i * 32 + lane];
        float4 e1 = e1p[i * 32 + lane];
        float4 w0 = ((const float4*)w0s)[m4];
        float4 w1 = ((const float4*)w1s)[m4];
        float4 i2 = ((const float4*)i2s)[m4];
        ins3(e0.x * w0.x, t[0], t[1], t[2]);
        ins3(e0.y * w0.y, t[0], t[1], t[2]);
        ins3(e0.z * w0.z, t[0], t[1], t[2]);
        ins3(e0.w * w0.w, t[0], t[1], t[2]);
        ins3(e1.x * w1.x, t[3], t[4], t[5]);
        ins3(e1.y * w1.y, t[3], t[4], t[5]);
        ins3(e1.z * w1.z, t[3], t[4], t[5]);
        ins3(e1.w * w1.w, t[3], t[4], t[5]);
        ins3(e0.x * e1.x * i2.x, t[6], t[7], t[8]);
        ins3(e0.y * e1.y * i2.y, t[6], t[7], t[8]);
        ins3(e0.z * e1.z * i2.z, t[6], t[7], t[8]);
        ins3(e0.w * e1.w * i2.w, t[6], t[7], t[8]);
    }
    #pragma unroll
    for (int off = 16; off; off >>= 1) {
        #pragma unroll
        for (int ch = 0; ch < 3; ch++) {
            float b0 = __shfl_xor_sync(0xffffffffu, t[ch * 3], off);
            float b1 = __shfl_xor_sync(0xffffffffu, t[ch * 3 + 1], off);
            float b2 = __shfl_xor_sync(0xffffffffu, t[ch * 3 + 2], off);
            merge3(t[ch * 3], t[ch * 3 + 1], t[ch * 3 + 2], b0, b1, b2);
        }
    }
    if (lane < 9) {
        float v = t[0];
        #pragma unroll
        for (int j = 1; j < 9; j++) v = (lane == j) ? t[j] : v;
        wpart[wid][lane] = v;
    }
    __syncthreads();
    if (tid < 48) {
        int rl2 = tid / 12, j = tid % 12;
        int k = j >> 2, pix = j & 3;
        int chn = (pix == 0) ? 0 : ((pix == 3) ? 1 : 2);
        int w0 = rl2 * 2;
        float a0 = wpart[w0][chn * 3], a1 = wpart[w0][chn * 3 + 1], a2 = wpart[w0][chn * 3 + 2];
        merge3(a0, a1, a2, wpart[w0 + 1][chn * 3], wpart[w0 + 1][chn * 3 + 1],
               wpart[w0 + 1][chn * 3 + 2]);
        float key = (k == 0) ? a0 : (k == 1) ? a1 : a2;
        int nn = (blk & 255) * 4 + rl2;
        float val;
        if (chn == 0)      { float q = key * w0s[nn]; val = q * q; }
        else if (chn == 1) { float q = key * w1s[nn]; val = q * q; }
        else               { val = key * i2s[nn]; }
        int rn = nn >> 5, cn = nn & 31;
        int hh = 2 * rn + (pix >> 1), ww = 2 * cn + (pix & 1);
        out[(((size_t)b * 3 + k) * HH + hh) * WW + ww] = val;
    }
}

// ================= launch ====================================================
extern "C" void kernel_launch(void* const* d_in, const int* in_sizes, int n_in,
                              void* d_out, int out_size) {
    const float* x = (const float*)d_in[0];
    const float* alpha = (const float*)d_in[1];
    float* out = (float*)d_out;

    cudaFuncSetAttribute(k2_gemm, cudaFuncAttributeMaxDynamicSharedMemorySize,
                         K2_SMEM);

    k1_norm<<<dim3(HH, BB), 256>>>(x);
    k2_gemm<<<dim3(36, 16), 256, K2_SMEM>>>(alpha);
    k3_rowsum<<<2048, 256>>>();
    k4_final<<<2048, 256>>>(out);
}